// round 6
// baseline (speedup 1.0000x reference)
#include <cuda_runtime.h>
#include <stdint.h>

// ============================================================================
// ModeloNeuralVasicek — neural Vasicek SDE Monte Carlo, exact-JAX-RNG replica.
// B=64, T=256, Q=256 paths, n_steps=2520, d_h=128, ctx=192, 7 maturities.
//
// RNG: JAX threefry, partitionable (default since 0.4.36):
//   keys[k] = threefry2x32(key=(0,1), counts=(0,k))       (both output words)
//   bits[i] = o0 ^ o1 of threefry2x32(keys[k], (0, i)),   i = b*256 + q
// Fallback (if rel_err is garbage → original scheme): counts split in halves,
// output concat — one structural flip next round.
// ============================================================================

#define NSTEPS 2520
#define BB 64
#define TT 256
#define F_DT 0.003968253968253968f
#define F_SQRT_DT 0.06299407883487119f
#define F_TSTEP (1.0f / 2519.0f)

// Device scratch (allocation-free rule: __device__ globals)
__device__ float g_H[BB * TT * 64];           // layernormed hidden (4 MiB)
__device__ float g_base[2][BB][128];          // ctx@W1[2:]+b1 per net/batch/unit
__device__ unsigned int g_keys[NSTEPS * 2];   // per-step threefry keys

// ---------------------------------------------------------------------------
// Threefry-2x32, 20 rounds — bit-exact JAX implementation
// ---------------------------------------------------------------------------
__device__ __forceinline__ void threefry2x32(uint32_t k0, uint32_t k1,
                                             uint32_t x0, uint32_t x1,
                                             uint32_t& o0, uint32_t& o1) {
    uint32_t ks2 = k0 ^ k1 ^ 0x1BD11BDAu;
    x0 += k0; x1 += k1;
#define TFR(r) { x0 += x1; x1 = __funnelshift_l(x1, x1, (r)); x1 ^= x0; }
    TFR(13) TFR(15) TFR(26) TFR(6)
    x0 += k1; x1 += ks2 + 1u;
    TFR(17) TFR(29) TFR(16) TFR(24)
    x0 += ks2; x1 += k0 + 2u;
    TFR(13) TFR(15) TFR(26) TFR(6)
    x0 += k0; x1 += k1 + 3u;
    TFR(17) TFR(29) TFR(16) TFR(24)
    x0 += k1; x1 += ks2 + 4u;
    TFR(13) TFR(15) TFR(26) TFR(6)
    x0 += ks2; x1 += k0 + 5u;
#undef TFR
    o0 = x0; o1 = x1;
}

// ---------------------------------------------------------------------------
// XLA ErfInv32 (Giles polynomial, both branches) — matches lax.erf_inv f32
// ---------------------------------------------------------------------------
__device__ __forceinline__ float erfinv_xla(float x) {
    float w = -log1pf(-x * x);
    float p;
    if (w < 5.0f) {
        w = w - 2.5f;
        p = 2.81022636e-08f;
        p = fmaf(p, w, 3.43273939e-07f);
        p = fmaf(p, w, -3.5233877e-06f);
        p = fmaf(p, w, -4.39150654e-06f);
        p = fmaf(p, w, 0.00021858087f);
        p = fmaf(p, w, -0.00125372503f);
        p = fmaf(p, w, -0.00417768164f);
        p = fmaf(p, w, 0.246640727f);
        p = fmaf(p, w, 1.50140941f);
    } else {
        w = sqrtf(w) - 3.0f;
        p = -0.000200214257f;
        p = fmaf(p, w, 0.000100950558f);
        p = fmaf(p, w, 0.00134934322f);
        p = fmaf(p, w, -0.00367342844f);
        p = fmaf(p, w, 0.00573950773f);
        p = fmaf(p, w, -0.0076224613f);
        p = fmaf(p, w, 0.00943887047f);
        p = fmaf(p, w, 1.00167406f);
        p = fmaf(p, w, 2.83297682f);
    }
    return p * x;
}

__device__ __forceinline__ float gelu_exact(float x) {
    // jax.nn.gelu(approximate=False): 0.5*x*(1+erf(x/sqrt(2)))
    return 0.5f * x * (1.0f + erff(x * 0.70710678118654752f));
}

// ---------------------------------------------------------------------------
// Packed f32x2 FFMA (only reachable via PTX on sm_103a)
// ---------------------------------------------------------------------------
__device__ __forceinline__ unsigned long long fma2(unsigned long long a,
                                                   unsigned long long b,
                                                   unsigned long long c) {
    unsigned long long d;
    asm("fma.rn.f32x2 %0, %1, %2, %3;" : "=l"(d) : "l"(a), "l"(b), "l"(c));
    return d;
}
__device__ __forceinline__ unsigned long long pack2(float lo, float hi) {
    unsigned long long v;
    asm("mov.b64 %0, {%1, %2};" : "=l"(v) : "f"(lo), "f"(hi));
    return v;
}
__device__ __forceinline__ float2 unpack2(unsigned long long v) {
    float2 r;
    asm("mov.b64 {%0, %1}, %2;" : "=f"(r.x), "=f"(r.y) : "l"(v));
    return r;
}

__device__ __forceinline__ float wredsum(float v) {
#pragma unroll
    for (int o = 16; o > 0; o >>= 1) v += __shfl_xor_sync(0xFFFFFFFFu, v, o);
    return v;
}

// ---------------------------------------------------------------------------
// Kernel 0: per-step threefry keys (partitionable/foldlike split of seed 1)
// ---------------------------------------------------------------------------
__global__ void keys_kernel() {
    int j = blockIdx.x * blockDim.x + threadIdx.x;
    if (j >= NSTEPS) return;
    uint32_t o0, o1;
    threefry2x32(0u, 1u, 0u, (uint32_t)j, o0, o1);
    g_keys[2 * j]     = o0;
    g_keys[2 * j + 1] = o1;
}

// ---------------------------------------------------------------------------
// Kernel 1: H = LN(tanh(X@Wp+bp)), one thread per (b,t)
// ---------------------------------------------------------------------------
__global__ void prep_kernel(const float* __restrict__ X,
                            const float* __restrict__ Wp,
                            const float* __restrict__ bp,
                            const float* __restrict__ ln_g,
                            const float* __restrict__ ln_b) {
    int b = blockIdx.x, t = threadIdx.x;
    float x0 = X[(b * TT + t) * 2 + 0];
    float x1 = X[(b * TT + t) * 2 + 1];
    float h[64];
    float s = 0.0f;
#pragma unroll
    for (int j = 0; j < 64; j++) {
        float v = fmaf(x1, Wp[64 + j], fmaf(x0, Wp[j], bp[j]));
        h[j] = tanhf(v);
        s += h[j];
    }
    float m = s * (1.0f / 64.0f);
    float vv = 0.0f;
#pragma unroll
    for (int j = 0; j < 64; j++) { float d = h[j] - m; vv = fmaf(d, d, vv); }
    vv *= (1.0f / 64.0f);
    float inv = rsqrtf(vv + 1e-5f);
    // match ref ordering: (h-m)/sqrt(v+eps)*g + b  (use division-equivalent mul; ulps ok)
    float den = sqrtf(vv + 1e-5f);
    (void)inv;
#pragma unroll
    for (int j = 0; j < 64; j++) {
        g_H[(b * TT + t) * 64 + j] = (h[j] - m) / den * ln_g[j] + ln_b[j];
    }
}

// ---------------------------------------------------------------------------
// Kernel 2: ctx (mean/std(ddof=1)/last over T) + base = ctx@W1[2:] + b1
// ---------------------------------------------------------------------------
__global__ void ctx_base_kernel(const float* __restrict__ mu_W1,
                                const float* __restrict__ mu_b1,
                                const float* __restrict__ si_W1,
                                const float* __restrict__ si_b1) {
    __shared__ float ctx[192];
    int b = blockIdx.x, tid = threadIdx.x;
    if (tid < 64) {
        int j = tid;
        const float* Hb = g_H + b * TT * 64;
        float s = 0.0f;
        for (int t = 0; t < TT; t++) s += Hb[t * 64 + j];
        float mean = s * (1.0f / 256.0f);
        float ss = 0.0f;
        for (int t = 0; t < TT; t++) { float d = Hb[t * 64 + j] - mean; ss = fmaf(d, d, ss); }
        float sd = sqrtf(ss * (1.0f / 255.0f));       // ddof=1
        ctx[j]       = mean;
        ctx[64 + j]  = sd;
        ctx[128 + j] = Hb[255 * 64 + j];
    }
    __syncthreads();
    int net = tid >> 7, j = tid & 127;
    const float* W1 = net ? si_W1 : mu_W1;
    float acc = (net ? si_b1 : mu_b1)[j];
    for (int i = 0; i < 192; i++)
        acc = fmaf(ctx[i], W1[(2 + i) * 128 + j], acc);
    g_base[net][b][j] = acc;
}

// ---------------------------------------------------------------------------
// Kernel 3: 2520-step SDE loop. One CTA per batch; thread q owns path q AND
// hidden unit (net = q>>7, j = q&127). W2 column resident in 64 u64 regs.
// ---------------------------------------------------------------------------
__global__ void __launch_bounds__(256, 1) sde_kernel(
    const float* __restrict__ r_ultimo, const float* __restrict__ mat,
    const float* __restrict__ mu_W1, const float* __restrict__ mu_W2,
    const float* __restrict__ mu_b2, const float* __restrict__ mu_W3,
    const float* __restrict__ mu_b3,
    const float* __restrict__ si_W1, const float* __restrict__ si_W2,
    const float* __restrict__ si_b2, const float* __restrict__ si_W3,
    const float* __restrict__ si_b3,
    float* __restrict__ out) {

    __shared__ __align__(16) float h1sh[2][128];
    __shared__ float rred[8];
    __shared__ float mred[8];
    __shared__ unsigned int skeys[NSTEPS * 2];

    const int b = blockIdx.x, tid = threadIdx.x;
    const int warp = tid >> 5, lane = tid & 31;

    for (int i = tid; i < NSTEPS * 2; i += 256) skeys[i] = g_keys[i];

    const int net = tid >> 7, j = tid & 127;
    const float* W1 = net ? si_W1 : mu_W1;
    const float* W2 = net ? si_W2 : mu_W2;
    const float w1a  = W1[j];            // row 0: r_mean weight
    const float w1b  = W1[128 + j];      // row 1: t weight
    const float base = g_base[net][b][j];
    const float b2j  = (net ? si_b2 : mu_b2)[j];
    const float w3   = (net ? si_W3 : mu_W3)[j];
    const float b3m  = mu_b3[0], b3s = si_b3[0];

    // W2 column j, rows (2i, 2i+1) packed as f32x2
    unsigned long long w2[64];
#pragma unroll
    for (int i = 0; i < 64; i++)
        w2[i] = pack2(W2[(2 * i) * 128 + j], W2[(2 * i + 1) * 128 + j]);

    float r = r_ultimo[b];
    float area = 0.0f;
    const uint32_t cnt = (uint32_t)(b * 256 + tid);

    for (int s = 0; s < NSTEPS; s++) {
        float t = (float)s * F_TSTEP;

        // --- r mean over 256 paths ---
        float rs = wredsum(r);
        if (lane == 0) rred[warp] = rs;
        __syncthreads();                                           // A
        float rmean = (((rred[0] + rred[1]) + (rred[2] + rred[3])) +
                       ((rred[4] + rred[5]) + (rred[6] + rred[7]))) * (1.0f / 256.0f);

        // --- layer 1 (collapsed): gelu(base + w1a*rmean + w1b*t) ---
        float h1 = gelu_exact(base + w1a * rmean + w1b * t);
        h1sh[net][j] = h1;
        __syncthreads();                                           // B

        // --- layer 2: packed FFMA2 over register-resident W2 column ---
        const unsigned long long* hp = (const unsigned long long*)(h1sh[net]);
        unsigned long long a0 = 0ull, a1 = 0ull, a2 = 0ull, a3 = 0ull;
#pragma unroll
        for (int i = 0; i < 64; i += 4) {
            a0 = fma2(hp[i + 0], w2[i + 0], a0);
            a1 = fma2(hp[i + 1], w2[i + 1], a1);
            a2 = fma2(hp[i + 2], w2[i + 2], a2);
            a3 = fma2(hp[i + 3], w2[i + 3], a3);
        }
        float2 f0 = unpack2(a0), f1 = unpack2(a1), f2 = unpack2(a2), f3 = unpack2(a3);
        float pre = b2j + (((f0.x + f0.y) + (f1.x + f1.y)) +
                           ((f2.x + f2.y) + (f3.x + f3.y)));
        float h2 = gelu_exact(pre);
        float c = h2 * w3;

        // --- layer 3 reduce (per net) ---
        float cs = wredsum(c);
        if (lane == 0) mred[warp] = cs;

        // threefry hoisted before the barrier (independent of reduction)
        uint32_t o0, o1;
        threefry2x32(skeys[2 * s], skeys[2 * s + 1], 0u, cnt, o0, o1);

        __syncthreads();                                           // C
        float mu  = (((mred[0] + mred[1]) + (mred[2] + mred[3]))) + b3m;
        float sp  = (((mred[4] + mred[5]) + (mred[6] + mred[7]))) + b3s;
        float si  = fmaxf(sp, 0.0f) + log1pf(expf(-fabsf(sp))) + 1e-5f;  // softplus + eps

        // --- exact JAX normal from bits ---
        uint32_t bits = o0 ^ o1;
        float f = __uint_as_float((bits >> 9) | 0x3F800000u) - 1.0f;     // [0,1)
        float u = fmaxf(fmaf(f, 2.0f, -0.99999994f), -0.99999994f);      // [lo,1)
        float z = 1.41421356237f * erfinv_xla(u);
        float dW = z * F_SQRT_DT;

        r = r + mu * F_DT + si * dW;
        area = fmaf(r, F_DT, area);
    }

    // --- finalize: mean(area) over paths, then 7 maturities ---
    float as = wredsum(area);
    if (lane == 0) rred[warp] = as;
    __syncthreads();
    if (tid < 7) {
        float ssum = (((rred[0] + rred[1]) + (rred[2] + rred[3])) +
                      ((rred[4] + rred[5]) + (rred[6] + rred[7])));
        float amean = ssum * (1.0f / 256.0f);
        float maxT = 0.0f;
#pragma unroll
        for (int m = 0; m < 7; m++) maxT = fmaxf(maxT, mat[m]);
        float frac = mat[tid] / (maxT + 1e-12f);
        out[b * 7 + tid] = (amean * frac) / (mat[tid] + 1e-12f);
    }
}

// ---------------------------------------------------------------------------
extern "C" void kernel_launch(void* const* d_in, const int* in_sizes, int n_in,
                              void* d_out, int out_size) {
    const float* X        = (const float*)d_in[0];
    const float* r_ultimo = (const float*)d_in[1];
    const float* mat      = (const float*)d_in[2];
    const float* Wp       = (const float*)d_in[3];
    const float* bp       = (const float*)d_in[4];
    const float* ln_g     = (const float*)d_in[5];
    const float* ln_b     = (const float*)d_in[6];
    const float* mu_W1    = (const float*)d_in[7];
    const float* mu_b1    = (const float*)d_in[8];
    const float* mu_W2    = (const float*)d_in[9];
    const float* mu_b2    = (const float*)d_in[10];
    const float* mu_W3    = (const float*)d_in[11];
    const float* mu_b3    = (const float*)d_in[12];
    const float* si_W1    = (const float*)d_in[13];
    const float* si_b1    = (const float*)d_in[14];
    const float* si_W2    = (const float*)d_in[15];
    const float* si_b2    = (const float*)d_in[16];
    const float* si_W3    = (const float*)d_in[17];
    const float* si_b3    = (const float*)d_in[18];
    float* out = (float*)d_out;

    keys_kernel<<<(NSTEPS + 255) / 256, 256>>>();
    prep_kernel<<<BB, TT>>>(X, Wp, bp, ln_g, ln_b);
    ctx_base_kernel<<<BB, 256>>>(mu_W1, mu_b1, si_W1, si_b1);
    sde_kernel<<<BB, 256>>>(r_ultimo, mat,
                            mu_W1, mu_W2, mu_b2, mu_W3, mu_b3,
                            si_W1, si_W2, si_b2, si_W3, si_b3,
                            out);
}

// round 7
// speedup vs baseline: 1.2856x; 1.2856x over previous
#include <cuda_runtime.h>
#include <stdint.h>

// ============================================================================
// ModeloNeuralVasicek — neural Vasicek SDE MC, exact-JAX-RNG, mean-collapsed.
// B=64, T=256, Q=256 paths, n_steps=2520, d_h=128, ctx=192, 7 maturities.
//
// Output depends on paths only through mean(r_s):
//   mean(r_{s+1}) = mean(r_s) + mu_s*DT + si_s * mean(dW_s)
// mean(dW_s) per (batch, step) is precomputed (RNG is state-independent).
// The 2520-step serial loop then carries one scalar + two 128-wide MLPs.
// ============================================================================

#define NSTEPS 2520
#define BB 64
#define TT 256
#define F_DT 0.003968253968253968f
#define F_SQRT_DT 0.06299407883487119f
#define F_TSTEP (1.0f / 2519.0f)

// Device scratch (allocation-free rule: __device__ globals)
__device__ float g_H[BB * TT * 64];        // layernormed hidden (4 MiB)
__device__ float g_base[2][BB][128];       // ctx@W1[2:]+b1 per net/batch/unit
__device__ float g_zbar[BB * NSTEPS];      // mean over paths of dW per (b,s)

// ---------------------------------------------------------------------------
// Threefry-2x32, 20 rounds — bit-exact JAX implementation
// ---------------------------------------------------------------------------
__device__ __forceinline__ void threefry2x32(uint32_t k0, uint32_t k1,
                                             uint32_t x0, uint32_t x1,
                                             uint32_t& o0, uint32_t& o1) {
    uint32_t ks2 = k0 ^ k1 ^ 0x1BD11BDAu;
    x0 += k0; x1 += k1;
#define TFR(r) { x0 += x1; x1 = __funnelshift_l(x1, x1, (r)); x1 ^= x0; }
    TFR(13) TFR(15) TFR(26) TFR(6)
    x0 += k1; x1 += ks2 + 1u;
    TFR(17) TFR(29) TFR(16) TFR(24)
    x0 += ks2; x1 += k0 + 2u;
    TFR(13) TFR(15) TFR(26) TFR(6)
    x0 += k0; x1 += k1 + 3u;
    TFR(17) TFR(29) TFR(16) TFR(24)
    x0 += k1; x1 += ks2 + 4u;
    TFR(13) TFR(15) TFR(26) TFR(6)
    x0 += ks2; x1 += k0 + 5u;
#undef TFR
    o0 = x0; o1 = x1;
}

// ---------------------------------------------------------------------------
// XLA ErfInv32 (Giles polynomial, both branches)
// ---------------------------------------------------------------------------
__device__ __forceinline__ float erfinv_xla(float x) {
    float w = -log1pf(-x * x);
    float p;
    if (w < 5.0f) {
        w = w - 2.5f;
        p = 2.81022636e-08f;
        p = fmaf(p, w, 3.43273939e-07f);
        p = fmaf(p, w, -3.5233877e-06f);
        p = fmaf(p, w, -4.39150654e-06f);
        p = fmaf(p, w, 0.00021858087f);
        p = fmaf(p, w, -0.00125372503f);
        p = fmaf(p, w, -0.00417768164f);
        p = fmaf(p, w, 0.246640727f);
        p = fmaf(p, w, 1.50140941f);
    } else {
        w = sqrtf(w) - 3.0f;
        p = -0.000200214257f;
        p = fmaf(p, w, 0.000100950558f);
        p = fmaf(p, w, 0.00134934322f);
        p = fmaf(p, w, -0.00367342844f);
        p = fmaf(p, w, 0.00573950773f);
        p = fmaf(p, w, -0.0076224613f);
        p = fmaf(p, w, 0.00943887047f);
        p = fmaf(p, w, 1.00167406f);
        p = fmaf(p, w, 2.83297682f);
    }
    return p * x;
}

__device__ __forceinline__ float gelu_exact(float x) {
    return 0.5f * x * (1.0f + erff(x * 0.70710678118654752f));
}

// ---------------------------------------------------------------------------
// Packed f32x2 FFMA (PTX-only on sm_103a)
// ---------------------------------------------------------------------------
__device__ __forceinline__ unsigned long long fma2(unsigned long long a,
                                                   unsigned long long b,
                                                   unsigned long long c) {
    unsigned long long d;
    asm("fma.rn.f32x2 %0, %1, %2, %3;" : "=l"(d) : "l"(a), "l"(b), "l"(c));
    return d;
}
__device__ __forceinline__ unsigned long long pack2(float lo, float hi) {
    unsigned long long v;
    asm("mov.b64 %0, {%1, %2};" : "=l"(v) : "f"(lo), "f"(hi));
    return v;
}
__device__ __forceinline__ float2 unpack2(unsigned long long v) {
    float2 r;
    asm("mov.b64 {%0, %1}, %2;" : "=f"(r.x), "=f"(r.y) : "l"(v));
    return r;
}

__device__ __forceinline__ float wredsum(float v) {
#pragma unroll
    for (int o = 16; o > 0; o >>= 1) v += __shfl_xor_sync(0xFFFFFFFFu, v, o);
    return v;
}

// ---------------------------------------------------------------------------
// Kernel 0: zbar[b][s] = mean over 256 paths of dW = z*sqrt_dt (exact JAX RNG)
// grid (NSTEPS, BB), 256 threads = one path each.
// ---------------------------------------------------------------------------
__global__ void zbar_kernel() {
    __shared__ float part[8];
    const int s = blockIdx.x, b = blockIdx.y, tid = threadIdx.x;
    const int warp = tid >> 5, lane = tid & 31;

    // step key: foldlike split of seed key (0,1) at count (0,s)
    uint32_t k0, k1;
    threefry2x32(0u, 1u, 0u, (uint32_t)s, k0, k1);
    // bits for element i = b*256 + tid: counts (0, i), output o0^o1
    uint32_t o0, o1;
    threefry2x32(k0, k1, 0u, (uint32_t)(b * 256 + tid), o0, o1);
    uint32_t bits = o0 ^ o1;

    float f = __uint_as_float((bits >> 9) | 0x3F800000u) - 1.0f;   // [0,1)
    float u = fmaxf(fmaf(f, 2.0f, -0.99999994f), -0.99999994f);    // [lo,1)
    float z = 1.41421356237f * erfinv_xla(u);
    float dw = z * F_SQRT_DT;

    float sum = wredsum(dw);
    if (lane == 0) part[warp] = sum;
    __syncthreads();
    if (tid == 0) {
        float t = (((part[0] + part[1]) + (part[2] + part[3])) +
                   ((part[4] + part[5]) + (part[6] + part[7])));
        g_zbar[b * NSTEPS + s] = t * (1.0f / 256.0f);
    }
}

// ---------------------------------------------------------------------------
// Kernel 1: H = LN(tanh(X@Wp+bp)), one thread per (b,t)
// ---------------------------------------------------------------------------
__global__ void prep_kernel(const float* __restrict__ X,
                            const float* __restrict__ Wp,
                            const float* __restrict__ bp,
                            const float* __restrict__ ln_g,
                            const float* __restrict__ ln_b) {
    int b = blockIdx.x, t = threadIdx.x;
    float x0 = X[(b * TT + t) * 2 + 0];
    float x1 = X[(b * TT + t) * 2 + 1];
    float h[64];
    float s = 0.0f;
#pragma unroll
    for (int j = 0; j < 64; j++) {
        float v = fmaf(x1, Wp[64 + j], fmaf(x0, Wp[j], bp[j]));
        h[j] = tanhf(v);
        s += h[j];
    }
    float m = s * (1.0f / 64.0f);
    float vv = 0.0f;
#pragma unroll
    for (int j = 0; j < 64; j++) { float d = h[j] - m; vv = fmaf(d, d, vv); }
    vv *= (1.0f / 64.0f);
    float den = sqrtf(vv + 1e-5f);
#pragma unroll
    for (int j = 0; j < 64; j++) {
        g_H[(b * TT + t) * 64 + j] = (h[j] - m) / den * ln_g[j] + ln_b[j];
    }
}

// ---------------------------------------------------------------------------
// Kernel 2: ctx (mean/std(ddof=1)/last over T) + base = ctx@W1[2:] + b1
// ---------------------------------------------------------------------------
__global__ void ctx_base_kernel(const float* __restrict__ mu_W1,
                                const float* __restrict__ mu_b1,
                                const float* __restrict__ si_W1,
                                const float* __restrict__ si_b1) {
    __shared__ float ctx[192];
    int b = blockIdx.x, tid = threadIdx.x;
    if (tid < 64) {
        int j = tid;
        const float* Hb = g_H + b * TT * 64;
        float s = 0.0f;
        for (int t = 0; t < TT; t++) s += Hb[t * 64 + j];
        float mean = s * (1.0f / 256.0f);
        float ss = 0.0f;
        for (int t = 0; t < TT; t++) { float d = Hb[t * 64 + j] - mean; ss = fmaf(d, d, ss); }
        float sd = sqrtf(ss * (1.0f / 255.0f));       // ddof=1
        ctx[j]       = mean;
        ctx[64 + j]  = sd;
        ctx[128 + j] = Hb[255 * 64 + j];
    }
    __syncthreads();
    int net = tid >> 7, j = tid & 127;
    const float* W1 = net ? si_W1 : mu_W1;
    float acc = (net ? si_b1 : mu_b1)[j];
    for (int i = 0; i < 192; i++)
        acc = fmaf(ctx[i], W1[(2 + i) * 128 + j], acc);
    g_base[net][b][j] = acc;
}

// ---------------------------------------------------------------------------
// Kernel 3: 2520-step scalar-mean SDE loop. One CTA per batch, 256 threads.
// Thread = hidden unit (net = tid>>7, j = tid&127). W2 column in 64 u64 regs.
// 2 barriers/step, no double buffering (each buffer's read window and next
// write are separated by a barrier).
// ---------------------------------------------------------------------------
__global__ void __launch_bounds__(256, 1) sde_kernel(
    const float* __restrict__ r_ultimo, const float* __restrict__ mat,
    const float* __restrict__ mu_W1, const float* __restrict__ mu_W2,
    const float* __restrict__ mu_b2, const float* __restrict__ mu_W3,
    const float* __restrict__ mu_b3,
    const float* __restrict__ si_W1, const float* __restrict__ si_W2,
    const float* __restrict__ si_b2, const float* __restrict__ si_W3,
    const float* __restrict__ si_b3,
    float* __restrict__ out) {

    __shared__ __align__(16) float h1sh[2][128];
    __shared__ float mred[8];
    __shared__ float zb[NSTEPS];

    const int b = blockIdx.x, tid = threadIdx.x;
    const int warp = tid >> 5, lane = tid & 31;

    for (int i = tid; i < NSTEPS; i += 256) zb[i] = g_zbar[b * NSTEPS + i];

    const int net = tid >> 7, j = tid & 127;
    const float* W1 = net ? si_W1 : mu_W1;
    const float* W2 = net ? si_W2 : mu_W2;
    const float w1a  = W1[j];            // row 0: r_mean weight
    const float w1b  = W1[128 + j];      // row 1: t weight
    const float base = g_base[net][b][j];
    const float b2j  = (net ? si_b2 : mu_b2)[j];
    const float w3   = (net ? si_W3 : mu_W3)[j];
    const float b3m  = mu_b3[0], b3s = si_b3[0];

    // W2 column j, rows (2i, 2i+1) packed as f32x2
    unsigned long long w2[64];
#pragma unroll
    for (int i = 0; i < 64; i++)
        w2[i] = pack2(W2[(2 * i) * 128 + j], W2[(2 * i + 1) * 128 + j]);

    float mean_r = r_ultimo[b];          // carried identically by all threads
    float asum = 0.0f;
    __syncthreads();                      // zb ready

    for (int s = 0; s < NSTEPS; s++) {
        float t = (float)s * F_TSTEP;

        // --- layer 1 (collapsed): gelu(base + w1a*mean_r + w1b*t) ---
        float h1 = gelu_exact(fmaf(w1b, t, fmaf(w1a, mean_r, base)));
        h1sh[net][j] = h1;
        __syncthreads();                                           // bar 1

        // --- layer 2: packed FFMA2, 8 independent accumulator chains,
        //     h1 read via 128-bit broadcasts ---
        const ulonglong2* hp = (const ulonglong2*)(h1sh[net]);
        unsigned long long a0 = 0ull, a1 = 0ull, a2 = 0ull, a3 = 0ull;
        unsigned long long a4 = 0ull, a5 = 0ull, a6 = 0ull, a7 = 0ull;
#pragma unroll
        for (int i = 0; i < 8; i++) {
            ulonglong2 h01 = hp[4 * i + 0];
            ulonglong2 h23 = hp[4 * i + 1];
            ulonglong2 h45 = hp[4 * i + 2];
            ulonglong2 h67 = hp[4 * i + 3];
            a0 = fma2(h01.x, w2[8 * i + 0], a0);
            a1 = fma2(h01.y, w2[8 * i + 1], a1);
            a2 = fma2(h23.x, w2[8 * i + 2], a2);
            a3 = fma2(h23.y, w2[8 * i + 3], a3);
            a4 = fma2(h45.x, w2[8 * i + 4], a4);
            a5 = fma2(h45.y, w2[8 * i + 5], a5);
            a6 = fma2(h67.x, w2[8 * i + 6], a6);
            a7 = fma2(h67.y, w2[8 * i + 7], a7);
        }
        a0 = fma2(a1, pack2(1.0f, 1.0f), a0); // a0 += a1 (keep packed)
        a2 = fma2(a3, pack2(1.0f, 1.0f), a2);
        a4 = fma2(a5, pack2(1.0f, 1.0f), a4);
        a6 = fma2(a7, pack2(1.0f, 1.0f), a6);
        float2 f0 = unpack2(a0), f2 = unpack2(a2), f4 = unpack2(a4), f6 = unpack2(a6);
        float pre = b2j + (((f0.x + f0.y) + (f2.x + f2.y)) +
                           ((f4.x + f4.y) + (f6.x + f6.y)));
        float h2 = gelu_exact(pre);
        float c = h2 * w3;

        // --- layer 3 reduce (per net: warps 0-3 mu, 4-7 si) ---
        float cs = wredsum(c);
        if (lane == 0) mred[warp] = cs;
        __syncthreads();                                           // bar 2

        float mu = (((mred[0] + mred[1]) + (mred[2] + mred[3]))) + b3m;
        float sp = (((mred[4] + mred[5]) + (mred[6] + mred[7]))) + b3s;
        float si = fmaxf(sp, 0.0f) + log1pf(expf(-fabsf(sp))) + 1e-5f;

        mean_r = fmaf(si, zb[s], fmaf(mu, F_DT, mean_r));
        asum = fmaf(mean_r, F_DT, asum);
    }

    if (tid < 7) {
        float maxT = 0.0f;
#pragma unroll
        for (int m = 0; m < 7; m++) maxT = fmaxf(maxT, mat[m]);
        float frac = mat[tid] / (maxT + 1e-12f);
        out[b * 7 + tid] = (asum * frac) / (mat[tid] + 1e-12f);
    }
}

// ---------------------------------------------------------------------------
extern "C" void kernel_launch(void* const* d_in, const int* in_sizes, int n_in,
                              void* d_out, int out_size) {
    const float* X        = (const float*)d_in[0];
    const float* r_ultimo = (const float*)d_in[1];
    const float* mat      = (const float*)d_in[2];
    const float* Wp       = (const float*)d_in[3];
    const float* bp       = (const float*)d_in[4];
    const float* ln_g     = (const float*)d_in[5];
    const float* ln_b     = (const float*)d_in[6];
    const float* mu_W1    = (const float*)d_in[7];
    const float* mu_b1    = (const float*)d_in[8];
    const float* mu_W2    = (const float*)d_in[9];
    const float* mu_b2    = (const float*)d_in[10];
    const float* mu_W3    = (const float*)d_in[11];
    const float* mu_b3    = (const float*)d_in[12];
    const float* si_W1    = (const float*)d_in[13];
    const float* si_b1    = (const float*)d_in[14];
    const float* si_W2    = (const float*)d_in[15];
    const float* si_b2    = (const float*)d_in[16];
    const float* si_W3    = (const float*)d_in[17];
    const float* si_b3    = (const float*)d_in[18];
    float* out = (float*)d_out;

    dim3 zgrid(NSTEPS, BB);
    zbar_kernel<<<zgrid, 256>>>();
    prep_kernel<<<BB, TT>>>(X, Wp, bp, ln_g, ln_b);
    ctx_base_kernel<<<BB, 256>>>(mu_W1, mu_b1, si_W1, si_b1);
    sde_kernel<<<BB, 256>>>(r_ultimo, mat,
                            mu_W1, mu_W2, mu_b2, mu_W3, mu_b3,
                            si_W1, si_W2, si_b2, si_W3, si_b3,
                            out);
}

// round 9
// speedup vs baseline: 1.3956x; 1.0856x over previous
#include <cuda_runtime.h>
#include <stdint.h>

// ============================================================================
// ModeloNeuralVasicek — neural Vasicek SDE MC, exact-JAX-RNG, mean-collapsed.
// B=64, T=256, Q=256 paths, n_steps=2520, d_h=128, ctx=192, 7 maturities.
//
// Output depends on paths only through mean(r_s):
//   mean(r_{s+1}) = mean(r_s) + mu_s*DT + si_s * mean(dW_s)
// mean(dW_s) per (batch, step) is precomputed (RNG is state-independent).
// The 2520-step serial loop then carries one scalar + two 128-wide MLPs.
// ============================================================================

#define NSTEPS 2520
#define BB 64
#define TT 256
#define F_DT 0.003968253968253968f
#define F_SQRT_DT 0.06299407883487119f
#define F_TSTEP (1.0f / 2519.0f)

// Device scratch (allocation-free rule: __device__ globals)
__device__ float g_H[BB * TT * 64];          // layernormed hidden (4 MiB)
__device__ float g_base[2][BB][128];         // ctx@W1[2:]+b1 per net/batch/unit
__device__ float g_zbar[BB * NSTEPS];        // mean over paths of dW per (b,s)
__device__ unsigned int g_keys[NSTEPS * 2];  // per-step threefry keys

// ---------------------------------------------------------------------------
// Threefry-2x32, 20 rounds — bit-exact JAX implementation
// ---------------------------------------------------------------------------
__device__ __forceinline__ void threefry2x32(uint32_t k0, uint32_t k1,
                                             uint32_t x0, uint32_t x1,
                                             uint32_t& o0, uint32_t& o1) {
    uint32_t ks2 = k0 ^ k1 ^ 0x1BD11BDAu;
    x0 += k0; x1 += k1;
#define TFR(r) { x0 += x1; x1 = __funnelshift_l(x1, x1, (r)); x1 ^= x0; }
    TFR(13) TFR(15) TFR(26) TFR(6)
    x0 += k1; x1 += ks2 + 1u;
    TFR(17) TFR(29) TFR(16) TFR(24)
    x0 += ks2; x1 += k0 + 2u;
    TFR(13) TFR(15) TFR(26) TFR(6)
    x0 += k0; x1 += k1 + 3u;
    TFR(17) TFR(29) TFR(16) TFR(24)
    x0 += k1; x1 += ks2 + 4u;
    TFR(13) TFR(15) TFR(26) TFR(6)
    x0 += ks2; x1 += k0 + 5u;
#undef TFR
    o0 = x0; o1 = x1;
}

// ---------------------------------------------------------------------------
// XLA ErfInv32 (Giles polynomial, both branches)
// ---------------------------------------------------------------------------
__device__ __forceinline__ float erfinv_xla(float x) {
    float w = -log1pf(-x * x);
    float p;
    if (w < 5.0f) {
        w = w - 2.5f;
        p = 2.81022636e-08f;
        p = fmaf(p, w, 3.43273939e-07f);
        p = fmaf(p, w, -3.5233877e-06f);
        p = fmaf(p, w, -4.39150654e-06f);
        p = fmaf(p, w, 0.00021858087f);
        p = fmaf(p, w, -0.00125372503f);
        p = fmaf(p, w, -0.00417768164f);
        p = fmaf(p, w, 0.246640727f);
        p = fmaf(p, w, 1.50140941f);
    } else {
        w = sqrtf(w) - 3.0f;
        p = -0.000200214257f;
        p = fmaf(p, w, 0.000100950558f);
        p = fmaf(p, w, 0.00134934322f);
        p = fmaf(p, w, -0.00367342844f);
        p = fmaf(p, w, 0.00573950773f);
        p = fmaf(p, w, -0.0076224613f);
        p = fmaf(p, w, 0.00943887047f);
        p = fmaf(p, w, 1.00167406f);
        p = fmaf(p, w, 2.83297682f);
    }
    return p * x;
}

__device__ __forceinline__ float gelu_exact(float x) {
    return 0.5f * x * (1.0f + erff(x * 0.70710678118654752f));
}

// ---------------------------------------------------------------------------
// Packed f32x2 FFMA (PTX-only on sm_103a)
// ---------------------------------------------------------------------------
__device__ __forceinline__ unsigned long long fma2(unsigned long long a,
                                                   unsigned long long b,
                                                   unsigned long long c) {
    unsigned long long d;
    asm("fma.rn.f32x2 %0, %1, %2, %3;" : "=l"(d) : "l"(a), "l"(b), "l"(c));
    return d;
}
__device__ __forceinline__ unsigned long long pack2(float lo, float hi) {
    unsigned long long v;
    asm("mov.b64 %0, {%1, %2};" : "=l"(v) : "f"(lo), "f"(hi));
    return v;
}
__device__ __forceinline__ float2 unpack2(unsigned long long v) {
    float2 r;
    asm("mov.b64 {%0, %1}, %2;" : "=f"(r.x), "=f"(r.y) : "l"(v));
    return r;
}

__device__ __forceinline__ float wredsum(float v) {
#pragma unroll
    for (int o = 16; o > 0; o >>= 1) v += __shfl_xor_sync(0xFFFFFFFFu, v, o);
    return v;
}

// ---------------------------------------------------------------------------
// Kernel 0: per-step threefry keys (partitionable/foldlike split of seed 1)
// ---------------------------------------------------------------------------
__global__ void keys_kernel() {
    int j = blockIdx.x * blockDim.x + threadIdx.x;
    if (j >= NSTEPS) return;
    uint32_t o0, o1;
    threefry2x32(0u, 1u, 0u, (uint32_t)j, o0, o1);
    g_keys[2 * j]     = o0;
    g_keys[2 * j + 1] = o1;
}

// ---------------------------------------------------------------------------
// Kernel 1: zbar[b][s] = mean over 256 paths of dW (exact JAX RNG)
// grid (NSTEPS, BB), 256 threads = one path each. Step keys precomputed.
// ---------------------------------------------------------------------------
__global__ void zbar_kernel() {
    __shared__ float part[8];
    const int s = blockIdx.x, b = blockIdx.y, tid = threadIdx.x;
    const int warp = tid >> 5, lane = tid & 31;

    uint32_t k0 = __ldg(&g_keys[2 * s]);
    uint32_t k1 = __ldg(&g_keys[2 * s + 1]);
    uint32_t o0, o1;
    threefry2x32(k0, k1, 0u, (uint32_t)(b * 256 + tid), o0, o1);
    uint32_t bits = o0 ^ o1;

    float f = __uint_as_float((bits >> 9) | 0x3F800000u) - 1.0f;   // [0,1)
    float u = fmaxf(fmaf(f, 2.0f, -0.99999994f), -0.99999994f);    // [lo,1)
    float z = 1.41421356237f * erfinv_xla(u);
    float dw = z * F_SQRT_DT;

    float sum = wredsum(dw);
    if (lane == 0) part[warp] = sum;
    __syncthreads();
    if (tid == 0) {
        float t = (((part[0] + part[1]) + (part[2] + part[3])) +
                   ((part[4] + part[5]) + (part[6] + part[7])));
        g_zbar[b * NSTEPS + s] = t * (1.0f / 256.0f);
    }
}

// ---------------------------------------------------------------------------
// Kernel 2: H = LN(tanh(X@Wp+bp)), one thread per (b,t)
// ---------------------------------------------------------------------------
__global__ void prep_kernel(const float* __restrict__ X,
                            const float* __restrict__ Wp,
                            const float* __restrict__ bp,
                            const float* __restrict__ ln_g,
                            const float* __restrict__ ln_b) {
    int b = blockIdx.x, t = threadIdx.x;
    float x0 = X[(b * TT + t) * 2 + 0];
    float x1 = X[(b * TT + t) * 2 + 1];
    float h[64];
    float s = 0.0f;
#pragma unroll
    for (int j = 0; j < 64; j++) {
        float v = fmaf(x1, Wp[64 + j], fmaf(x0, Wp[j], bp[j]));
        h[j] = tanhf(v);
        s += h[j];
    }
    float m = s * (1.0f / 64.0f);
    float vv = 0.0f;
#pragma unroll
    for (int j = 0; j < 64; j++) { float d = h[j] - m; vv = fmaf(d, d, vv); }
    vv *= (1.0f / 64.0f);
    float den = sqrtf(vv + 1e-5f);
#pragma unroll
    for (int j = 0; j < 64; j++) {
        g_H[(b * TT + t) * 64 + j] = (h[j] - m) / den * ln_g[j] + ln_b[j];
    }
}

// ---------------------------------------------------------------------------
// Kernel 3: ctx (mean/std(ddof=1)/last over T) + base = ctx@W1[2:] + b1
// ---------------------------------------------------------------------------
__global__ void ctx_base_kernel(const float* __restrict__ mu_W1,
                                const float* __restrict__ mu_b1,
                                const float* __restrict__ si_W1,
                                const float* __restrict__ si_b1) {
    __shared__ float ctx[192];
    int b = blockIdx.x, tid = threadIdx.x;
    if (tid < 64) {
        int j = tid;
        const float* Hb = g_H + b * TT * 64;
        float s = 0.0f;
        for (int t = 0; t < TT; t++) s += Hb[t * 64 + j];
        float mean = s * (1.0f / 256.0f);
        float ss = 0.0f;
        for (int t = 0; t < TT; t++) { float d = Hb[t * 64 + j] - mean; ss = fmaf(d, d, ss); }
        float sd = sqrtf(ss * (1.0f / 255.0f));       // ddof=1
        ctx[j]       = mean;
        ctx[64 + j]  = sd;
        ctx[128 + j] = Hb[255 * 64 + j];
    }
    __syncthreads();
    int net = tid >> 7, j = tid & 127;
    const float* W1 = net ? si_W1 : mu_W1;
    float acc = (net ? si_b1 : mu_b1)[j];
    for (int i = 0; i < 192; i++)
        acc = fmaf(ctx[i], W1[(2 + i) * 128 + j], acc);
    g_base[net][b][j] = acc;
}

// ---------------------------------------------------------------------------
// Kernel 4: 2520-step scalar-mean SDE loop. One CTA per batch, 256 threads.
// Thread = hidden unit (net = tid>>7, j = tid&127). W2 column in 64 u64 regs.
// Exactly 2 barriers/step; single-buffered smem is safe (each buffer's read
// window and next write are separated by a barrier).
// ---------------------------------------------------------------------------
__global__ void __launch_bounds__(256, 1) sde_kernel(
    const float* __restrict__ r_ultimo, const float* __restrict__ mat,
    const float* __restrict__ mu_W1, const float* __restrict__ mu_W2,
    const float* __restrict__ mu_b2, const float* __restrict__ mu_W3,
    const float* __restrict__ mu_b3,
    const float* __restrict__ si_W1, const float* __restrict__ si_W2,
    const float* __restrict__ si_b2, const float* __restrict__ si_W3,
    const float* __restrict__ si_b3,
    float* __restrict__ out) {

    __shared__ __align__(16) float h1sh[2][128];
    __shared__ __align__(32) float mred[8];
    __shared__ float zb[NSTEPS];

    const int b = blockIdx.x, tid = threadIdx.x;
    const int warp = tid >> 5, lane = tid & 31;

    for (int i = tid; i < NSTEPS; i += 256) zb[i] = g_zbar[b * NSTEPS + i];

    const int net = tid >> 7, j = tid & 127;
    const float* W1 = net ? si_W1 : mu_W1;
    const float* W2 = net ? si_W2 : mu_W2;
    const float w1a  = W1[j];            // row 0: r_mean weight
    const float w1b  = W1[128 + j];      // row 1: t weight
    const float base = g_base[net][b][j];
    const float b2j  = (net ? si_b2 : mu_b2)[j];
    const float w3   = (net ? si_W3 : mu_W3)[j];
    const float b3m  = mu_b3[0], b3s = si_b3[0];

    // W2 column j, rows (2i, 2i+1) packed as f32x2
    unsigned long long w2[64];
#pragma unroll
    for (int i = 0; i < 64; i++)
        w2[i] = pack2(W2[(2 * i) * 128 + j], W2[(2 * i + 1) * 128 + j]);

    float mean_r = r_ultimo[b];          // carried identically by all threads
    float asum = 0.0f;
    __syncthreads();                      // zb ready

    for (int s = 0; s < NSTEPS; s++) {
        // bt is independent of mean_r — off the serial critical path
        float bt = fmaf(w1b, (float)s * F_TSTEP, base);
        float zbs = zb[s];

        // --- layer 1 (collapsed): gelu(bt + w1a*mean_r) ---
        float h1 = gelu_exact(fmaf(w1a, mean_r, bt));
        h1sh[net][j] = h1;
        __syncthreads();                                           // bar 1

        // --- layer 2: packed FFMA2, 8 independent accumulator chains ---
        const ulonglong2* hp = (const ulonglong2*)(h1sh[net]);
        unsigned long long a0 = 0ull, a1 = 0ull, a2 = 0ull, a3 = 0ull;
        unsigned long long a4 = 0ull, a5 = 0ull, a6 = 0ull, a7 = 0ull;
#pragma unroll
        for (int i = 0; i < 8; i++) {
            ulonglong2 h01 = hp[4 * i + 0];
            ulonglong2 h23 = hp[4 * i + 1];
            ulonglong2 h45 = hp[4 * i + 2];
            ulonglong2 h67 = hp[4 * i + 3];
            a0 = fma2(h01.x, w2[8 * i + 0], a0);
            a1 = fma2(h01.y, w2[8 * i + 1], a1);
            a2 = fma2(h23.x, w2[8 * i + 2], a2);
            a3 = fma2(h23.y, w2[8 * i + 3], a3);
            a4 = fma2(h45.x, w2[8 * i + 4], a4);
            a5 = fma2(h45.y, w2[8 * i + 5], a5);
            a6 = fma2(h67.x, w2[8 * i + 6], a6);
            a7 = fma2(h67.y, w2[8 * i + 7], a7);
        }
        const unsigned long long one2 = 0x3F8000003F800000ull;     // (1.0f,1.0f)
        a0 = fma2(a1, one2, a0);
        a2 = fma2(a3, one2, a2);
        a4 = fma2(a5, one2, a4);
        a6 = fma2(a7, one2, a6);
        float2 f0 = unpack2(a0), f2 = unpack2(a2), f4 = unpack2(a4), f6 = unpack2(a6);
        float pre = b2j + (((f0.x + f0.y) + (f2.x + f2.y)) +
                           ((f4.x + f4.y) + (f6.x + f6.y)));
        float h2 = gelu_exact(pre);
        float c = h2 * w3;

        // --- layer 3 reduce (per net: warps 0-3 mu, 4-7 si) ---
        float cs = wredsum(c);
        if (lane == 0) mred[warp] = cs;
        __syncthreads();                                           // bar 2

        float4 mlo = *(const float4*)&mred[0];
        float4 mhi = *(const float4*)&mred[4];
        float mu = ((mlo.x + mlo.y) + (mlo.z + mlo.w)) + b3m;
        float sp = ((mhi.x + mhi.y) + (mhi.z + mhi.w)) + b3s;
        // softplus via fast intrinsics (rel err ~1e-7, budget 1e-3)
        float si = fmaxf(sp, 0.0f) + __logf(1.0f + __expf(-fabsf(sp))) + 1e-5f;

        mean_r = fmaf(si, zbs, fmaf(mu, F_DT, mean_r));
        asum = fmaf(mean_r, F_DT, asum);
    }

    if (tid < 7) {
        float maxT = 0.0f;
#pragma unroll
        for (int m = 0; m < 7; m++) maxT = fmaxf(maxT, mat[m]);
        float frac = mat[tid] / (maxT + 1e-12f);
        out[b * 7 + tid] = (asum * frac) / (mat[tid] + 1e-12f);
    }
}

// ---------------------------------------------------------------------------
extern "C" void kernel_launch(void* const* d_in, const int* in_sizes, int n_in,
                              void* d_out, int out_size) {
    const float* X        = (const float*)d_in[0];
    const float* r_ultimo = (const float*)d_in[1];
    const float* mat      = (const float*)d_in[2];
    const float* Wp       = (const float*)d_in[3];
    const float* bp       = (const float*)d_in[4];
    const float* ln_g     = (const float*)d_in[5];
    const float* ln_b     = (const float*)d_in[6];
    const float* mu_W1    = (const float*)d_in[7];
    const float* mu_b1    = (const float*)d_in[8];
    const float* mu_W2    = (const float*)d_in[9];
    const float* mu_b2    = (const float*)d_in[10];
    const float* mu_W3    = (const float*)d_in[11];
    const float* mu_b3    = (const float*)d_in[12];
    const float* si_W1    = (const float*)d_in[13];
    const float* si_b1    = (const float*)d_in[14];
    const float* si_W2    = (const float*)d_in[15];
    const float* si_b2    = (const float*)d_in[16];
    const float* si_W3    = (const float*)d_in[17];
    const float* si_b3    = (const float*)d_in[18];
    float* out = (float*)d_out;

    keys_kernel<<<(NSTEPS + 255) / 256, 256>>>();
    dim3 zgrid(NSTEPS, BB);
    zbar_kernel<<<zgrid, 256>>>();
    prep_kernel<<<BB, TT>>>(X, Wp, bp, ln_g, ln_b);
    ctx_base_kernel<<<BB, 256>>>(mu_W1, mu_b1, si_W1, si_b1);
    sde_kernel<<<BB, 256>>>(r_ultimo, mat,
                            mu_W1, mu_W2, mu_b2, mu_W3, mu_b3,
                            si_W1, si_W2, si_b2, si_W3, si_b3,
                            out);
}

// round 10
// speedup vs baseline: 1.5126x; 1.0838x over previous
#include <cuda_runtime.h>
#include <stdint.h>

// ============================================================================
// ModeloNeuralVasicek — neural Vasicek SDE MC, exact-JAX-RNG, mean-collapsed.
// B=64, T=256, Q=256 paths, n_steps=2520, d_h=128, ctx=192, 7 maturities.
//
// Output depends on paths only through mean(r_s):
//   mean(r_{s+1}) = mean(r_s) + mu_s*DT + si_s * mean(dW_s)
// mean(dW_s) per (batch, step) is precomputed (RNG is state-independent).
// The 2520-step serial loop then carries one scalar + two 128-wide MLPs.
//
// This round: integer redux.sync for the layer-3 warp reduce (fixed-point,
// scale 2^21) and incremental carry of the layer-1 argument u.
// ============================================================================

#define NSTEPS 2520
#define BB 64
#define TT 256
#define F_DT 0.003968253968253968f
#define F_SQRT_DT 0.06299407883487119f
#define F_TSTEP (1.0f / 2519.0f)
#define FIX_SCALE 2097152.0f          // 2^21
#define FIX_INV   (1.0f / 2097152.0f)

// Device scratch (allocation-free rule: __device__ globals)
__device__ float g_H[BB * TT * 64];          // layernormed hidden (4 MiB)
__device__ float g_base[2][BB][128];         // ctx@W1[2:]+b1 per net/batch/unit
__device__ float g_zbar[BB * NSTEPS];        // mean over paths of dW per (b,s)
__device__ unsigned int g_keys[NSTEPS * 2];  // per-step threefry keys

// ---------------------------------------------------------------------------
// Threefry-2x32, 20 rounds — bit-exact JAX implementation
// ---------------------------------------------------------------------------
__device__ __forceinline__ void threefry2x32(uint32_t k0, uint32_t k1,
                                             uint32_t x0, uint32_t x1,
                                             uint32_t& o0, uint32_t& o1) {
    uint32_t ks2 = k0 ^ k1 ^ 0x1BD11BDAu;
    x0 += k0; x1 += k1;
#define TFR(r) { x0 += x1; x1 = __funnelshift_l(x1, x1, (r)); x1 ^= x0; }
    TFR(13) TFR(15) TFR(26) TFR(6)
    x0 += k1; x1 += ks2 + 1u;
    TFR(17) TFR(29) TFR(16) TFR(24)
    x0 += ks2; x1 += k0 + 2u;
    TFR(13) TFR(15) TFR(26) TFR(6)
    x0 += k0; x1 += k1 + 3u;
    TFR(17) TFR(29) TFR(16) TFR(24)
    x0 += k1; x1 += ks2 + 4u;
    TFR(13) TFR(15) TFR(26) TFR(6)
    x0 += ks2; x1 += k0 + 5u;
#undef TFR
    o0 = x0; o1 = x1;
}

// ---------------------------------------------------------------------------
// XLA ErfInv32 (Giles polynomial, both branches)
// ---------------------------------------------------------------------------
__device__ __forceinline__ float erfinv_xla(float x) {
    float w = -log1pf(-x * x);
    float p;
    if (w < 5.0f) {
        w = w - 2.5f;
        p = 2.81022636e-08f;
        p = fmaf(p, w, 3.43273939e-07f);
        p = fmaf(p, w, -3.5233877e-06f);
        p = fmaf(p, w, -4.39150654e-06f);
        p = fmaf(p, w, 0.00021858087f);
        p = fmaf(p, w, -0.00125372503f);
        p = fmaf(p, w, -0.00417768164f);
        p = fmaf(p, w, 0.246640727f);
        p = fmaf(p, w, 1.50140941f);
    } else {
        w = sqrtf(w) - 3.0f;
        p = -0.000200214257f;
        p = fmaf(p, w, 0.000100950558f);
        p = fmaf(p, w, 0.00134934322f);
        p = fmaf(p, w, -0.00367342844f);
        p = fmaf(p, w, 0.00573950773f);
        p = fmaf(p, w, -0.0076224613f);
        p = fmaf(p, w, 0.00943887047f);
        p = fmaf(p, w, 1.00167406f);
        p = fmaf(p, w, 2.83297682f);
    }
    return p * x;
}

__device__ __forceinline__ float gelu_exact(float x) {
    return 0.5f * x * (1.0f + erff(x * 0.70710678118654752f));
}

// ---------------------------------------------------------------------------
// Packed f32x2 FFMA (PTX-only on sm_103a)
// ---------------------------------------------------------------------------
__device__ __forceinline__ unsigned long long fma2(unsigned long long a,
                                                   unsigned long long b,
                                                   unsigned long long c) {
    unsigned long long d;
    asm("fma.rn.f32x2 %0, %1, %2, %3;" : "=l"(d) : "l"(a), "l"(b), "l"(c));
    return d;
}
__device__ __forceinline__ unsigned long long pack2(float lo, float hi) {
    unsigned long long v;
    asm("mov.b64 %0, {%1, %2};" : "=l"(v) : "f"(lo), "f"(hi));
    return v;
}
__device__ __forceinline__ float2 unpack2(unsigned long long v) {
    float2 r;
    asm("mov.b64 {%0, %1}, %2;" : "=f"(r.x), "=f"(r.y) : "l"(v));
    return r;
}

__device__ __forceinline__ float wredsum(float v) {
#pragma unroll
    for (int o = 16; o > 0; o >>= 1) v += __shfl_xor_sync(0xFFFFFFFFu, v, o);
    return v;
}

// Integer warp reduction — single instruction on sm_80+ (f32 variant is NOT
// supported on sm_103, the s32 one is).
__device__ __forceinline__ int redux_add_s32(int v) {
    int r;
    asm("redux.sync.add.s32 %0, %1, 0xffffffff;" : "=r"(r) : "r"(v));
    return r;
}

// ---------------------------------------------------------------------------
// Kernel 0: per-step threefry keys (partitionable/foldlike split of seed 1)
// ---------------------------------------------------------------------------
__global__ void keys_kernel() {
    int j = blockIdx.x * blockDim.x + threadIdx.x;
    if (j >= NSTEPS) return;
    uint32_t o0, o1;
    threefry2x32(0u, 1u, 0u, (uint32_t)j, o0, o1);
    g_keys[2 * j]     = o0;
    g_keys[2 * j + 1] = o1;
}

// ---------------------------------------------------------------------------
// Kernel 1: zbar[b][s] = mean over 256 paths of dW (exact JAX RNG)
// grid (NSTEPS, BB), 256 threads = one path each. Step keys precomputed.
// ---------------------------------------------------------------------------
__global__ void zbar_kernel() {
    __shared__ float part[8];
    const int s = blockIdx.x, b = blockIdx.y, tid = threadIdx.x;
    const int warp = tid >> 5, lane = tid & 31;

    uint32_t k0 = __ldg(&g_keys[2 * s]);
    uint32_t k1 = __ldg(&g_keys[2 * s + 1]);
    uint32_t o0, o1;
    threefry2x32(k0, k1, 0u, (uint32_t)(b * 256 + tid), o0, o1);
    uint32_t bits = o0 ^ o1;

    float f = __uint_as_float((bits >> 9) | 0x3F800000u) - 1.0f;   // [0,1)
    float u = fmaxf(fmaf(f, 2.0f, -0.99999994f), -0.99999994f);    // [lo,1)
    float z = 1.41421356237f * erfinv_xla(u);
    float dw = z * F_SQRT_DT;

    float sum = wredsum(dw);
    if (lane == 0) part[warp] = sum;
    __syncthreads();
    if (tid == 0) {
        float t = (((part[0] + part[1]) + (part[2] + part[3])) +
                   ((part[4] + part[5]) + (part[6] + part[7])));
        g_zbar[b * NSTEPS + s] = t * (1.0f / 256.0f);
    }
}

// ---------------------------------------------------------------------------
// Kernel 2: H = LN(tanh(X@Wp+bp)), one thread per (b,t)
// ---------------------------------------------------------------------------
__global__ void prep_kernel(const float* __restrict__ X,
                            const float* __restrict__ Wp,
                            const float* __restrict__ bp,
                            const float* __restrict__ ln_g,
                            const float* __restrict__ ln_b) {
    int b = blockIdx.x, t = threadIdx.x;
    float x0 = X[(b * TT + t) * 2 + 0];
    float x1 = X[(b * TT + t) * 2 + 1];
    float h[64];
    float s = 0.0f;
#pragma unroll
    for (int j = 0; j < 64; j++) {
        float v = fmaf(x1, Wp[64 + j], fmaf(x0, Wp[j], bp[j]));
        h[j] = tanhf(v);
        s += h[j];
    }
    float m = s * (1.0f / 64.0f);
    float vv = 0.0f;
#pragma unroll
    for (int j = 0; j < 64; j++) { float d = h[j] - m; vv = fmaf(d, d, vv); }
    vv *= (1.0f / 64.0f);
    float den = sqrtf(vv + 1e-5f);
#pragma unroll
    for (int j = 0; j < 64; j++) {
        g_H[(b * TT + t) * 64 + j] = (h[j] - m) / den * ln_g[j] + ln_b[j];
    }
}

// ---------------------------------------------------------------------------
// Kernel 3: ctx (mean/std(ddof=1)/last over T) + base = ctx@W1[2:] + b1
// ---------------------------------------------------------------------------
__global__ void ctx_base_kernel(const float* __restrict__ mu_W1,
                                const float* __restrict__ mu_b1,
                                const float* __restrict__ si_W1,
                                const float* __restrict__ si_b1) {
    __shared__ float ctx[192];
    int b = blockIdx.x, tid = threadIdx.x;
    if (tid < 64) {
        int j = tid;
        const float* Hb = g_H + b * TT * 64;
        float s = 0.0f;
        for (int t = 0; t < TT; t++) s += Hb[t * 64 + j];
        float mean = s * (1.0f / 256.0f);
        float ss = 0.0f;
        for (int t = 0; t < TT; t++) { float d = Hb[t * 64 + j] - mean; ss = fmaf(d, d, ss); }
        float sd = sqrtf(ss * (1.0f / 255.0f));       // ddof=1
        ctx[j]       = mean;
        ctx[64 + j]  = sd;
        ctx[128 + j] = Hb[255 * 64 + j];
    }
    __syncthreads();
    int net = tid >> 7, j = tid & 127;
    const float* W1 = net ? si_W1 : mu_W1;
    float acc = (net ? si_b1 : mu_b1)[j];
    for (int i = 0; i < 192; i++)
        acc = fmaf(ctx[i], W1[(2 + i) * 128 + j], acc);
    g_base[net][b][j] = acc;
}

// ---------------------------------------------------------------------------
// Kernel 4: 2520-step scalar-mean SDE loop. One CTA per batch, 256 threads.
// Thread = hidden unit (net = tid>>7, j = tid&127). W2 column in 64 u64 regs.
// Exactly 2 barriers/step; single-buffered smem is safe (each buffer's read
// window and next write are separated by a barrier).
// ---------------------------------------------------------------------------
__global__ void __launch_bounds__(256, 1) sde_kernel(
    const float* __restrict__ r_ultimo, const float* __restrict__ mat,
    const float* __restrict__ mu_W1, const float* __restrict__ mu_W2,
    const float* __restrict__ mu_b2, const float* __restrict__ mu_W3,
    const float* __restrict__ mu_b3,
    const float* __restrict__ si_W1, const float* __restrict__ si_W2,
    const float* __restrict__ si_b2, const float* __restrict__ si_W3,
    const float* __restrict__ si_b3,
    float* __restrict__ out) {

    __shared__ __align__(16) float h1sh[2][128];
    __shared__ __align__(32) float mred[8];
    __shared__ float zb[NSTEPS];

    const int b = blockIdx.x, tid = threadIdx.x;
    const int warp = tid >> 5, lane = tid & 31;

    for (int i = tid; i < NSTEPS; i += 256) zb[i] = g_zbar[b * NSTEPS + i];

    const int net = tid >> 7, j = tid & 127;
    const float* W1 = net ? si_W1 : mu_W1;
    const float* W2 = net ? si_W2 : mu_W2;
    const float w1a  = W1[j];            // row 0: r_mean weight
    const float w1b  = W1[128 + j];      // row 1: t weight
    const float base = g_base[net][b][j];
    const float b2j  = (net ? si_b2 : mu_b2)[j];
    const float w3s  = (net ? si_W3 : mu_W3)[j] * FIX_SCALE;  // pre-scaled
    const float b3m  = mu_b3[0], b3s = si_b3[0];
    const float du   = w1b * F_TSTEP;    // per-step increment of w1b*t

    // W2 column j, rows (2i, 2i+1) packed as f32x2
    unsigned long long w2[64];
#pragma unroll
    for (int i = 0; i < 64; i++)
        w2[i] = pack2(W2[(2 * i) * 128 + j], W2[(2 * i + 1) * 128 + j]);

    float mean_r = r_ultimo[b];          // carried identically by all threads
    float asum = 0.0f;
    // u_s = base + w1a*mean_r_s + w1b*t_s, carried incrementally
    float u = fmaf(w1a, mean_r, base);   // t_0 = 0
    __syncthreads();                      // zb ready

    for (int s = 0; s < NSTEPS; s++) {
        float zbs = zb[s];

        // --- layer 1 (collapsed): gelu(u) ---
        float h1 = gelu_exact(u);
        h1sh[net][j] = h1;
        float upd = u + du;                // next-step bias, off critical path
        __syncthreads();                                           // bar 1

        // --- layer 2: packed FFMA2, 8 independent accumulator chains ---
        const ulonglong2* hp = (const ulonglong2*)(h1sh[net]);
        unsigned long long a0 = 0ull, a1 = 0ull, a2 = 0ull, a3 = 0ull;
        unsigned long long a4 = 0ull, a5 = 0ull, a6 = 0ull, a7 = 0ull;
#pragma unroll
        for (int i = 0; i < 8; i++) {
            ulonglong2 h01 = hp[4 * i + 0];
            ulonglong2 h23 = hp[4 * i + 1];
            ulonglong2 h45 = hp[4 * i + 2];
            ulonglong2 h67 = hp[4 * i + 3];
            a0 = fma2(h01.x, w2[8 * i + 0], a0);
            a1 = fma2(h01.y, w2[8 * i + 1], a1);
            a2 = fma2(h23.x, w2[8 * i + 2], a2);
            a3 = fma2(h23.y, w2[8 * i + 3], a3);
            a4 = fma2(h45.x, w2[8 * i + 4], a4);
            a5 = fma2(h45.y, w2[8 * i + 5], a5);
            a6 = fma2(h67.x, w2[8 * i + 6], a6);
            a7 = fma2(h67.y, w2[8 * i + 7], a7);
        }
        const unsigned long long one2 = 0x3F8000003F800000ull;     // (1.0f,1.0f)
        a0 = fma2(a1, one2, a0);
        a2 = fma2(a3, one2, a2);
        a4 = fma2(a5, one2, a4);
        a6 = fma2(a7, one2, a6);
        float2 f0 = unpack2(a0), f2 = unpack2(a2), f4 = unpack2(a4), f6 = unpack2(a6);
        float pre = b2j + (((f0.x + f0.y) + (f2.x + f2.y)) +
                           ((f4.x + f4.y) + (f6.x + f6.y)));
        float h2 = gelu_exact(pre);

        // --- layer 3 reduce (per net): fixed-point single-instruction redux ---
        int ci = __float2int_rn(h2 * w3s);          // c * 2^21, round nearest
        int cs = redux_add_s32(ci);
        if (lane == 0) mred[warp] = (float)cs * FIX_INV;
        __syncthreads();                                           // bar 2

        float4 mlo = *(const float4*)&mred[0];
        float4 mhi = *(const float4*)&mred[4];
        float mu = ((mlo.x + mlo.y) + (mlo.z + mlo.w)) + b3m;
        float sp = ((mhi.x + mhi.y) + (mhi.z + mhi.w)) + b3s;
        // softplus via fast intrinsics (rel err ~1e-7, budget 1e-3)
        float si = fmaxf(sp, 0.0f) + __logf(1.0f + __expf(-fabsf(sp))) + 1e-5f;

        // dmr independent of mean_r: shortest path into next layer-1 arg
        float dmr = fmaf(si, zbs, mu * F_DT);
        u = fmaf(w1a, dmr, upd);
        mean_r += dmr;
        asum = fmaf(mean_r, F_DT, asum);
    }

    if (tid < 7) {
        float maxT = 0.0f;
#pragma unroll
        for (int m = 0; m < 7; m++) maxT = fmaxf(maxT, mat[m]);
        float frac = mat[tid] / (maxT + 1e-12f);
        out[b * 7 + tid] = (asum * frac) / (mat[tid] + 1e-12f);
    }
}

// ---------------------------------------------------------------------------
extern "C" void kernel_launch(void* const* d_in, const int* in_sizes, int n_in,
                              void* d_out, int out_size) {
    const float* X        = (const float*)d_in[0];
    const float* r_ultimo = (const float*)d_in[1];
    const float* mat      = (const float*)d_in[2];
    const float* Wp       = (const float*)d_in[3];
    const float* bp       = (const float*)d_in[4];
    const float* ln_g     = (const float*)d_in[5];
    const float* ln_b     = (const float*)d_in[6];
    const float* mu_W1    = (const float*)d_in[7];
    const float* mu_b1    = (const float*)d_in[8];
    const float* mu_W2    = (const float*)d_in[9];
    const float* mu_b2    = (const float*)d_in[10];
    const float* mu_W3    = (const float*)d_in[11];
    const float* mu_b3    = (const float*)d_in[12];
    const float* si_W1    = (const float*)d_in[13];
    const float* si_b1    = (const float*)d_in[14];
    const float* si_W2    = (const float*)d_in[15];
    const float* si_b2    = (const float*)d_in[16];
    const float* si_W3    = (const float*)d_in[17];
    const float* si_b3    = (const float*)d_in[18];
    float* out = (float*)d_out;

    keys_kernel<<<(NSTEPS + 255) / 256, 256>>>();
    dim3 zgrid(NSTEPS, BB);
    zbar_kernel<<<zgrid, 256>>>();
    prep_kernel<<<BB, TT>>>(X, Wp, bp, ln_g, ln_b);
    ctx_base_kernel<<<BB, 256>>>(mu_W1, mu_b1, si_W1, si_b1);
    sde_kernel<<<BB, 256>>>(r_ultimo, mat,
                            mu_W1, mu_W2, mu_b2, mu_W3, mu_b3,
                            si_W1, si_W2, si_b2, si_W3, si_b3,
                            out);
}